// round 12
// baseline (speedup 1.0000x reference)
#include <cuda_runtime.h>
#include <cstdint>
#include <math.h>

#define N_NODES 50000
#define N_EDGES 600000
#define DIM     128
#define DIM4    32
#define NLAYER  5
#define BN_EPS  1e-5f

// ---------------- device scratch ----------------
__device__ float g_h  [N_NODES * DIM];           // node features (BN output)
__device__ float g_h2 [N_NODES * DIM];           // GEMM2 output (pre-BN)
__device__ uint32_t g_aggh[N_NODES * 64];        // agg hi plane
__device__ uint32_t g_aggl[N_NODES * 64];        // agg lo plane
__device__ uint32_t g_midh[N_NODES * 128];       // mid hi plane (N x 256)
__device__ uint32_t g_midl[N_NODES * 128];
__device__ int   g_counts[N_NODES];
__device__ int   g_row[N_NODES + 1];
__device__ int   g_cursor[N_NODES];
__device__ int   g_bsums[64];
__device__ int   g_csr_src[N_EDGES];
__device__ int   g_csr_ea [N_EDGES];
__device__ float g_stats[2 * DIM];
__device__ uint32_t g_w1h[81920], g_w1l[81920], g_w2h[81920], g_w2l[81920];

// ---------------- helpers ----------------
__device__ __forceinline__ uint32_t smem_u32(const void* p) {
    uint32_t a;
    asm("{ .reg .u64 t; cvta.to.shared.u64 t, %1; cvt.u32.u64 %0, t; }"
        : "=r"(a) : "l"(p));
    return a;
}
__device__ __forceinline__ uint32_t pack_hi(float a, float b) {
    return __byte_perm(__float_as_uint(a), __float_as_uint(b), 0x7632);
}
__device__ __forceinline__ uint32_t pack_lo(float a, float b) {
    float ra = a - __uint_as_float(__float_as_uint(a) & 0xFFFF0000u);
    float rb = b - __uint_as_float(__float_as_uint(b) & 0xFFFF0000u);
    uint32_t r;
    asm("cvt.rn.bf16x2.f32 %0, %1, %2;" : "=r"(r) : "f"(rb), "f"(ra));
    return r;
}
__device__ __forceinline__ void ldsm4(uint32_t* r, uint32_t addr) {
    asm volatile("ldmatrix.sync.aligned.m8n8.x4.shared.b16 {%0,%1,%2,%3}, [%4];"
        : "=r"(r[0]), "=r"(r[1]), "=r"(r[2]), "=r"(r[3]) : "r"(addr));
}
__device__ __forceinline__ void ldsm2t(uint32_t* r, uint32_t addr) {
    asm volatile("ldmatrix.sync.aligned.m8n8.x2.trans.shared.b16 {%0,%1}, [%2];"
        : "=r"(r[0]), "=r"(r[1]) : "r"(addr));
}
__device__ __forceinline__ void mma_bf16(float* c, const uint32_t* a, const uint32_t* b) {
    asm volatile("mma.sync.aligned.m16n8k16.row.col.f32.bf16.bf16.f32 "
        "{%0,%1,%2,%3}, {%4,%5,%6,%7}, {%8,%9}, {%0,%1,%2,%3};"
        : "+f"(c[0]), "+f"(c[1]), "+f"(c[2]), "+f"(c[3])
        : "r"(a[0]), "r"(a[1]), "r"(a[2]), "r"(a[3]), "r"(b[0]), "r"(b[1]));
}

// ---------------- setup kernels ----------------
__global__ void k_init_h(const int* __restrict__ x,
                         const float* __restrict__ ae,
                         const float* __restrict__ ce,
                         const float* __restrict__ he) {
    int i = blockIdx.x * blockDim.x + threadIdx.x;
    if (i < N_NODES) g_counts[i] = 0;
    if (i >= N_NODES * DIM4) return;
    int r = i >> 5, q = i & 31;
    int a = x[r * 3 + 0];
    int c = x[r * 3 + 1];
    int h = x[r * 3 + 2];
    float4 v  = ((const float4*)ae)[a * DIM4 + q];
    float4 v2 = ((const float4*)ce)[c * DIM4 + q];
    float4 v3 = ((const float4*)he)[h * DIM4 + q];
    v.x += v2.x + v3.x; v.y += v2.y + v3.y;
    v.z += v2.z + v3.z; v.w += v2.w + v3.w;
    ((float4*)g_h)[i] = v;
}

__global__ void k_wconv(const float* __restrict__ W1, const float* __restrict__ W2) {
    int t = blockIdx.x * blockDim.x + threadIdx.x;
    if (t >= 81920) return;
    float2 a = ((const float2*)W1)[t];
    float2 b = ((const float2*)W2)[t];
    g_w1h[t] = pack_hi(a.x, a.y);
    g_w1l[t] = pack_lo(a.x, a.y);
    g_w2h[t] = pack_hi(b.x, b.y);
    g_w2l[t] = pack_lo(b.x, b.y);
}

__global__ void k_hist(const int* __restrict__ ei) {
    int e = blockIdx.x * blockDim.x + threadIdx.x;
    if (e >= N_EDGES) return;
    atomicAdd(&g_counts[ei[N_EDGES + e]], 1);
}
__global__ void k_scan1() {
    __shared__ int sm[1024];
    int t = threadIdx.x;
    int gid = blockIdx.x * 1024 + t;
    int v = (gid < N_NODES) ? g_counts[gid] : 0;
    sm[t] = v;
    __syncthreads();
    for (int off = 1; off < 1024; off <<= 1) {
        int add = (t >= off) ? sm[t - off] : 0;
        __syncthreads();
        sm[t] += add;
        __syncthreads();
    }
    if (gid < N_NODES) g_row[gid] = sm[t] - v;
    if (t == 1023) g_bsums[blockIdx.x] = sm[1023];
}
__global__ void k_scan2(int nb) {
    __shared__ int sm[64];
    int t = threadIdx.x;
    int v = (t < nb) ? g_bsums[t] : 0;
    sm[t] = v;
    __syncthreads();
    for (int off = 1; off < 64; off <<= 1) {
        int add = (t >= off) ? sm[t - off] : 0;
        __syncthreads();
        sm[t] += add;
        __syncthreads();
    }
    if (t < nb) g_bsums[t] = sm[t] - v;
}
__global__ void k_scan3() {
    int gid = blockIdx.x * blockDim.x + threadIdx.x;
    if (gid < N_NODES) {
        int r = g_row[gid] + g_bsums[gid >> 10];
        g_row[gid] = r;
        g_cursor[gid] = r;
    }
    if (gid == 0) g_row[N_NODES] = N_EDGES;
}
__global__ void k_scatter(const int* __restrict__ ei, const int* __restrict__ ea) {
    int e = blockIdx.x * blockDim.x + threadIdx.x;
    if (e >= N_EDGES) return;
    int d = ei[N_EDGES + e];
    int p = atomicAdd(&g_cursor[d], 1);
    g_csr_src[p] = ei[e];
    g_csr_ea[p]  = ea[2 * e] + (ea[2 * e + 1] << 3);
}

// one warp per node; emits agg as hi/lo bf16 planes; block 0 zeroes stats
__global__ void __launch_bounds__(256) k_agg(const float* __restrict__ e1l,
                                             const float* __restrict__ e2l) {
    __shared__ float4 se[10 * DIM4];
    int tid = threadIdx.x;
    if (blockIdx.x == 0 && tid < 2 * DIM) g_stats[tid] = 0.f;
    for (int i = tid; i < 10 * DIM4; i += 256) {
        const float* src = (i < 6 * DIM4) ? (e1l + i * 4) : (e2l + (i - 6 * DIM4) * 4);
        se[i] = *(const float4*)src;
    }
    __syncthreads();
    int warp = tid >> 5, lane = tid & 31;
    int v = blockIdx.x * 8 + warp;
    if (v >= N_NODES) return;
    int s0 = g_row[v], s1 = g_row[v + 1];
    float4 acc = make_float4(0.f, 0.f, 0.f, 0.f);
    for (int e = s0; e < s1; e++) {
        int s  = g_csr_src[e];
        int at = g_csr_ea[e];
        float4 hv = ((const float4*)g_h)[s * DIM4 + lane];
        float4 t1 = se[(at & 7) * DIM4 + lane];
        float4 t2 = se[6 * DIM4 + (at >> 3) * DIM4 + lane];
        acc.x += hv.x + t1.x + t2.x;
        acc.y += hv.y + t1.y + t2.y;
        acc.z += hv.z + t1.z + t2.z;
        acc.w += hv.w + t1.w + t2.w;
    }
    uint2 hi, lo;
    hi.x = pack_hi(acc.x, acc.y); hi.y = pack_hi(acc.z, acc.w);
    lo.x = pack_lo(acc.x, acc.y); lo.y = pack_lo(acc.z, acc.w);
    ((uint2*)g_aggh)[v * 32 + lane] = hi;
    ((uint2*)g_aggl)[v * 32 + lane] = lo;
}

// ---------------- GEMM geometry ----------------
#define LDT 136
#define ROWB (LDT * 2)            // 272B smem row stride
#define PLANE (128 * ROWB)        // 34816
#define SMEM1 (4 * PLANE)         // 139264
#define SMEM2 (6 * PLANE)         // 208896

// GEMM1: mid = relu(agg @ W1 + b1) -> mid hi/lo planes. grid (2,391).
__global__ void __launch_bounds__(256, 1) k_hmma1(
    int M,
    const uint32_t* __restrict__ ah_g, const uint32_t* __restrict__ al_g,
    const uint32_t* __restrict__ wh, const uint32_t* __restrict__ wl,
    const float* __restrict__ bias) {
    extern __shared__ char smem[];
    const uint32_t sb = smem_u32(smem);
    const uint32_t AH = sb, AL = sb + PLANE, BH = sb + 2 * PLANE, BL = sb + 3 * PLANE;
    char* pAH = smem;
    char* pAL = smem + PLANE;
    char* pBH = smem + 2 * PLANE;
    char* pBL = smem + 3 * PLANE;

    const int tid = threadIdx.x, wid = tid >> 5, lane = tid & 31;
    const int wm = wid >> 2, wn = wid & 3;
    const int rowBase = blockIdx.y << 7;
    const int bx = blockIdx.x;

    // A fill: pure uint4 copy from agg planes
#pragma unroll
    for (int it = 0; it < 8; it++) {
        int g = tid + it * 256;
        int r = g >> 4, c = g & 15;
        uint4 hv = make_uint4(0, 0, 0, 0), lv = hv;
        if (rowBase + r < M) {
            size_t src = (size_t)(rowBase + r) * 16 + c;
            hv = ((const uint4*)ah_g)[src];
            lv = ((const uint4*)al_g)[src];
        }
        int off = r * ROWB + c * 16;
        *(uint4*)(pAH + off) = hv;
        *(uint4*)(pAL + off) = lv;
    }
    // B fill: coalesced copy
#pragma unroll
    for (int it = 0; it < 8; it++) {
        int g = tid + it * 256;
        int k = g >> 4, c = g & 15;
        size_t src = (size_t)k * 32 + bx * 16 + c;
        int off = k * ROWB + c * 16;
        *(uint4*)(pBH + off) = ((const uint4*)wh)[src];
        *(uint4*)(pBL + off) = ((const uint4*)wl)[src];
    }
    __syncthreads();

    float acc[4][4][4];
#pragma unroll
    for (int i = 0; i < 4; i++)
#pragma unroll
        for (int j = 0; j < 4; j++)
#pragma unroll
            for (int k = 0; k < 4; k++) acc[i][j][k] = 0.f;

    const int arow = wm * 64 + (lane & 15);
    const int acolSel = (lane >> 4) << 3;
    const int brow = lane & 15;
#pragma unroll
    for (int kk = 0; kk < 8; kk++) {
        uint32_t ah[4][4], al[4][4], bh[4][2], bl[4][2];
        int acol = kk * 16 + acolSel;
#pragma unroll
        for (int mi = 0; mi < 4; mi++) {
            uint32_t ao = (uint32_t)((arow + mi * 16) * ROWB + acol * 2);
            ldsm4(ah[mi], AH + ao);
            ldsm4(al[mi], AL + ao);
        }
#pragma unroll
        for (int ni = 0; ni < 4; ni++) {
            uint32_t bo = (uint32_t)((kk * 16 + brow) * ROWB + (wn * 32 + ni * 8) * 2);
            ldsm2t(bh[ni], BH + bo);
            ldsm2t(bl[ni], BL + bo);
        }
#pragma unroll
        for (int mi = 0; mi < 4; mi++)
#pragma unroll
            for (int ni = 0; ni < 4; ni++) {
                mma_bf16(acc[mi][ni], ah[mi], bh[ni]);
                mma_bf16(acc[mi][ni], ah[mi], bl[ni]);
                mma_bf16(acc[mi][ni], al[mi], bh[ni]);
            }
    }

    // epilogue: bias + relu, pack to mid hi/lo planes
    const int rBase = rowBase + wm * 64 + (lane >> 2);
    const int cBase = bx * 128 + wn * 32 + (lane & 3) * 2;
#pragma unroll
    for (int mi = 0; mi < 4; mi++)
#pragma unroll
        for (int h = 0; h < 2; h++) {
            int row = rBase + mi * 16 + h * 8;
            if (row < M) {
#pragma unroll
                for (int ni = 0; ni < 4; ni++) {
                    int col = cBase + ni * 8;
                    float ox = fmaxf(acc[mi][ni][2 * h + 0] + bias[col], 0.f);
                    float oy = fmaxf(acc[mi][ni][2 * h + 1] + bias[col + 1], 0.f);
                    size_t di = (size_t)row * 128 + (col >> 1);
                    g_midh[di] = pack_hi(ox, oy);
                    g_midl[di] = pack_lo(ox, oy);
                }
            }
        }
}

// GEMM2: h2 = mid @ W2 + b2, fused BN-stats. grid 391. K=256, all-copy fills.
__global__ void __launch_bounds__(256, 1) k_hmma2(
    int M,
    const uint32_t* __restrict__ ah_g, const uint32_t* __restrict__ al_g,
    const uint32_t* __restrict__ wh, const uint32_t* __restrict__ wl,
    const float* __restrict__ bias, float* __restrict__ C) {
    extern __shared__ char smem[];
    const uint32_t sb = smem_u32(smem);
    const uint32_t AH = sb, AL = sb + PLANE, BH = sb + 2 * PLANE, BL = sb + 4 * PLANE;
    char* pAH = smem;
    char* pAL = smem + PLANE;
    char* pBH = smem + 2 * PLANE;
    char* pBL = smem + 4 * PLANE;

    const int tid = threadIdx.x, wid = tid >> 5, lane = tid & 31;
    const int wm = wid >> 2, wn = wid & 3;
    const int rowBase = blockIdx.x << 7;

    // B preload: all 256 k-rows
#pragma unroll
    for (int it = 0; it < 16; it++) {
        int g = tid + it * 256;
        int k = g >> 4, c = g & 15;
        size_t src = (size_t)k * 16 + c;
        int off = k * ROWB + c * 16;
        *(uint4*)(pBH + off) = ((const uint4*)wh)[src];
        *(uint4*)(pBL + off) = ((const uint4*)wl)[src];
    }

    float acc[4][4][4];
#pragma unroll
    for (int i = 0; i < 4; i++)
#pragma unroll
        for (int j = 0; j < 4; j++)
#pragma unroll
            for (int k = 0; k < 4; k++) acc[i][j][k] = 0.f;

    const int arow = wm * 64 + (lane & 15);
    const int acolSel = (lane >> 4) << 3;
    const int brow = lane & 15;

    for (int ch = 0; ch < 2; ch++) {
        if (ch) __syncthreads();
        // A fill: pure uint4 copy from mid planes (row = 32 uint4; chunk at ch*16)
#pragma unroll
        for (int it = 0; it < 8; it++) {
            int g = tid + it * 256;
            int r = g >> 4, c = g & 15;
            uint4 hv = make_uint4(0, 0, 0, 0), lv = hv;
            if (rowBase + r < M) {
                size_t src = (size_t)(rowBase + r) * 32 + ch * 16 + c;
                hv = ((const uint4*)ah_g)[src];
                lv = ((const uint4*)al_g)[src];
            }
            int off = r * ROWB + c * 16;
            *(uint4*)(pAH + off) = hv;
            *(uint4*)(pAL + off) = lv;
        }
        __syncthreads();

#pragma unroll
        for (int kk = 0; kk < 8; kk++) {
            uint32_t ah[4][4], al[4][4], bh[4][2], bl[4][2];
            int acol = kk * 16 + acolSel;
#pragma unroll
            for (int mi = 0; mi < 4; mi++) {
                uint32_t ao = (uint32_t)((arow + mi * 16) * ROWB + acol * 2);
                ldsm4(ah[mi], AH + ao);
                ldsm4(al[mi], AL + ao);
            }
#pragma unroll
            for (int ni = 0; ni < 4; ni++) {
                uint32_t bo = (uint32_t)((ch * 128 + kk * 16 + brow) * ROWB
                                         + (wn * 32 + ni * 8) * 2);
                ldsm2t(bh[ni], BH + bo);
                ldsm2t(bl[ni], BL + bo);
            }
#pragma unroll
            for (int mi = 0; mi < 4; mi++)
#pragma unroll
                for (int ni = 0; ni < 4; ni++) {
                    mma_bf16(acc[mi][ni], ah[mi], bh[ni]);
                    mma_bf16(acc[mi][ni], ah[mi], bl[ni]);
                    mma_bf16(acc[mi][ni], al[mi], bh[ni]);
                }
        }
    }

    // epilogue: store + column sums/sumsq -> g_stats
    const int rBase = rowBase + wm * 64 + (lane >> 2);
    const int cBase = wn * 32 + (lane & 3) * 2;
    float csum[4][2], csq[4][2];
#pragma unroll
    for (int ni = 0; ni < 4; ni++) {
        csum[ni][0] = csum[ni][1] = 0.f;
        csq[ni][0] = csq[ni][1] = 0.f;
    }
#pragma unroll
    for (int mi = 0; mi < 4; mi++)
#pragma unroll
        for (int h = 0; h < 2; h++) {
            int row = rBase + mi * 16 + h * 8;
            if (row < M) {
#pragma unroll
                for (int ni = 0; ni < 4; ni++) {
                    int col = cBase + ni * 8;
                    float2 o;
                    o.x = acc[mi][ni][2 * h + 0] + bias[col];
                    o.y = acc[mi][ni][2 * h + 1] + bias[col + 1];
                    *(float2*)(C + (size_t)row * 128 + col) = o;
                    csum[ni][0] += o.x; csq[ni][0] += o.x * o.x;
                    csum[ni][1] += o.y; csq[ni][1] += o.y * o.y;
                }
            }
        }
#pragma unroll
    for (int ni = 0; ni < 4; ni++)
#pragma unroll
        for (int p = 0; p < 2; p++) {
            float s = csum[ni][p], q = csq[ni][p];
            s += __shfl_xor_sync(0xFFFFFFFF, s, 4);
            q += __shfl_xor_sync(0xFFFFFFFF, q, 4);
            s += __shfl_xor_sync(0xFFFFFFFF, s, 8);
            q += __shfl_xor_sync(0xFFFFFFFF, q, 8);
            s += __shfl_xor_sync(0xFFFFFFFF, s, 16);
            q += __shfl_xor_sync(0xFFFFFFFF, q, 16);
            if ((lane >> 2) == 0) {
                int col = cBase + ni * 8 + p;
                atomicAdd(&g_stats[col], s);
                atomicAdd(&g_stats[DIM + col], q);
            }
        }
}

// ---------------- BN apply (every layer; relu on all but last) ----------------
__global__ void k_bn(const float* __restrict__ h2,
                     const float* __restrict__ gamma,
                     const float* __restrict__ beta,
                     float* __restrict__ out, int relu) {
    __shared__ float sc[DIM], sh[DIM];
    int tid = threadIdx.x;
    if (tid < DIM) {
        float mu  = g_stats[tid] * (1.0f / N_NODES);
        float var = g_stats[DIM + tid] * (1.0f / N_NODES) - mu * mu;
        float s = gamma[tid] * rsqrtf(var + BN_EPS);
        sc[tid] = s;
        sh[tid] = beta[tid] - mu * s;
    }
    __syncthreads();
    int i = blockIdx.x * blockDim.x + tid;
    if (i >= N_NODES * DIM4) return;
    int c = (i & 31) * 4;
    float4 v = ((const float4*)h2)[i];
    v.x = v.x * sc[c + 0] + sh[c + 0];
    v.y = v.y * sc[c + 1] + sh[c + 1];
    v.z = v.z * sc[c + 2] + sh[c + 2];
    v.w = v.w * sc[c + 3] + sh[c + 3];
    if (relu) {
        v.x = fmaxf(v.x, 0.f); v.y = fmaxf(v.y, 0.f);
        v.z = fmaxf(v.z, 0.f); v.w = fmaxf(v.w, 0.f);
    }
    ((float4*)out)[i] = v;
}

// ---------------- launch ----------------
extern "C" void kernel_launch(void* const* d_in, const int* in_sizes, int n_in,
                              void* d_out, int out_size) {
    const int*   x     = (const int*)d_in[0];
    const int*   ei    = (const int*)d_in[1];
    const int*   ea    = (const int*)d_in[2];
    const float* atom  = (const float*)d_in[3];
    const float* chir  = (const float*)d_in[4];
    const float* hyb   = (const float*)d_in[5];
    const float* e1    = (const float*)d_in[6];
    const float* e2    = (const float*)d_in[7];
    const float* W1    = (const float*)d_in[8];
    const float* b1    = (const float*)d_in[9];
    const float* W2    = (const float*)d_in[10];
    const float* b2    = (const float*)d_in[11];
    const float* gamma = (const float*)d_in[12];
    const float* beta  = (const float*)d_in[13];
    float* out = (float*)d_out;

    float *pH2, *pH;
    uint32_t *pAh, *pAl, *pMh, *pMl, *pW1h, *pW1l, *pW2h, *pW2l;
    cudaGetSymbolAddress((void**)&pH2,  g_h2);
    cudaGetSymbolAddress((void**)&pH,   g_h);
    cudaGetSymbolAddress((void**)&pAh,  g_aggh);
    cudaGetSymbolAddress((void**)&pAl,  g_aggl);
    cudaGetSymbolAddress((void**)&pMh,  g_midh);
    cudaGetSymbolAddress((void**)&pMl,  g_midl);
    cudaGetSymbolAddress((void**)&pW1h, g_w1h);
    cudaGetSymbolAddress((void**)&pW1l, g_w1l);
    cudaGetSymbolAddress((void**)&pW2h, g_w2h);
    cudaGetSymbolAddress((void**)&pW2l, g_w2l);

    cudaFuncSetAttribute(k_hmma1, cudaFuncAttributeMaxDynamicSharedMemorySize, SMEM1);
    cudaFuncSetAttribute(k_hmma2, cudaFuncAttributeMaxDynamicSharedMemorySize, SMEM2);

    const int TPB = 256;
    int nbE = (N_EDGES + TPB - 1) / TPB;
    int nbN = (N_NODES + TPB - 1) / TPB;
    int nbF4 = (N_NODES * DIM4) / TPB;

    k_init_h<<<nbF4, TPB>>>(x, atom, chir, hyb);
    k_wconv<<<320, 256>>>(W1, W2);
    k_hist<<<nbE, TPB>>>(ei);
    int scanBlocks = (N_NODES + 1023) / 1024;
    k_scan1<<<scanBlocks, 1024>>>();
    k_scan2<<<1, 64>>>(scanBlocks);
    k_scan3<<<nbN, TPB>>>();
    k_scatter<<<nbE, TPB>>>(ei, ea);

    int gemmRows = (N_NODES + 127) / 128;   // 391
    for (int l = 0; l < NLAYER; l++) {
        k_agg<<<(N_NODES + 7) / 8, 256>>>(e1 + (size_t)l * 6 * DIM,
                                          e2 + (size_t)l * 4 * DIM);
        k_hmma1<<<dim3(2, gemmRows), 256, SMEM1>>>(
            N_NODES, pAh, pAl, pW1h + l * 16384, pW1l + l * 16384,
            b1 + (size_t)l * 2 * DIM);
        k_hmma2<<<gemmRows, 256, SMEM2>>>(
            N_NODES, pMh, pMl, pW2h + l * 16384, pW2l + l * 16384,
            b2 + (size_t)l * DIM, pH2);
        int last = (l == NLAYER - 1);
        k_bn<<<nbF4, TPB>>>(pH2, gamma + (size_t)l * DIM, beta + (size_t)l * DIM,
                            last ? out : pH, last ? 0 : 1);
    }
}

// round 15
// speedup vs baseline: 1.2461x; 1.2461x over previous
#include <cuda_runtime.h>
#include <cstdint>
#include <math.h>

#define N_NODES 50000
#define N_EDGES 600000
#define DIM     128
#define DIM4    32
#define NLAYER  5
#define BN_EPS  1e-5f

// ---------------- device scratch ----------------
__device__ float g_h  [N_NODES * DIM];           // node features (BN output)
__device__ float g_h2 [N_NODES * DIM];           // fused-GEMM output (pre-BN)
__device__ uint32_t g_aggh[N_NODES * 64];        // agg hi plane
__device__ uint32_t g_aggl[N_NODES * 64];        // agg lo plane
__device__ int   g_counts[N_NODES];
__device__ int   g_row[N_NODES + 1];
__device__ int   g_cursor[N_NODES];
__device__ int   g_bsums[64];
__device__ int   g_csr_src[N_EDGES];
__device__ int   g_csr_ea [N_EDGES];
__device__ float g_stats[2 * DIM];
__device__ uint32_t g_w1h[81920], g_w1l[81920], g_w2h[81920], g_w2l[81920];

// ---------------- helpers ----------------
__device__ __forceinline__ uint32_t smem_u32(const void* p) {
    uint32_t a;
    asm("{ .reg .u64 t; cvta.to.shared.u64 t, %1; cvt.u32.u64 %0, t; }"
        : "=r"(a) : "l"(p));
    return a;
}
__device__ __forceinline__ uint32_t pack_hi(float a, float b) {
    return __byte_perm(__float_as_uint(a), __float_as_uint(b), 0x7632);
}
__device__ __forceinline__ uint32_t pack_lo(float a, float b) {
    float ra = a - __uint_as_float(__float_as_uint(a) & 0xFFFF0000u);
    float rb = b - __uint_as_float(__float_as_uint(b) & 0xFFFF0000u);
    uint32_t r;
    asm("cvt.rn.bf16x2.f32 %0, %1, %2;" : "=r"(r) : "f"(rb), "f"(ra));
    return r;
}
__device__ __forceinline__ void ldsm4(uint32_t* r, uint32_t addr) {
    asm volatile("ldmatrix.sync.aligned.m8n8.x4.shared.b16 {%0,%1,%2,%3}, [%4];"
        : "=r"(r[0]), "=r"(r[1]), "=r"(r[2]), "=r"(r[3]) : "r"(addr));
}
__device__ __forceinline__ void ldsm2t(uint32_t* r, uint32_t addr) {
    asm volatile("ldmatrix.sync.aligned.m8n8.x2.trans.shared.b16 {%0,%1}, [%2];"
        : "=r"(r[0]), "=r"(r[1]) : "r"(addr));
}
__device__ __forceinline__ void mma_bf16(float* c, const uint32_t* a, const uint32_t* b) {
    asm volatile("mma.sync.aligned.m16n8k16.row.col.f32.bf16.bf16.f32 "
        "{%0,%1,%2,%3}, {%4,%5,%6,%7}, {%8,%9}, {%0,%1,%2,%3};"
        : "+f"(c[0]), "+f"(c[1]), "+f"(c[2]), "+f"(c[3])
        : "r"(a[0]), "r"(a[1]), "r"(a[2]), "r"(a[3]), "r"(b[0]), "r"(b[1]));
}

// ---------------- setup kernels ----------------
__global__ void k_init_h(const int* __restrict__ x,
                         const float* __restrict__ ae,
                         const float* __restrict__ ce,
                         const float* __restrict__ he) {
    int i = blockIdx.x * blockDim.x + threadIdx.x;
    if (i < N_NODES) g_counts[i] = 0;
    if (i >= N_NODES * DIM4) return;
    int r = i >> 5, q = i & 31;
    int a = x[r * 3 + 0];
    int c = x[r * 3 + 1];
    int h = x[r * 3 + 2];
    float4 v  = ((const float4*)ae)[a * DIM4 + q];
    float4 v2 = ((const float4*)ce)[c * DIM4 + q];
    float4 v3 = ((const float4*)he)[h * DIM4 + q];
    v.x += v2.x + v3.x; v.y += v2.y + v3.y;
    v.z += v2.z + v3.z; v.w += v2.w + v3.w;
    ((float4*)g_h)[i] = v;
}

__global__ void k_wconv(const float* __restrict__ W1, const float* __restrict__ W2) {
    int t = blockIdx.x * blockDim.x + threadIdx.x;
    if (t >= 81920) return;
    float2 a = ((const float2*)W1)[t];
    float2 b = ((const float2*)W2)[t];
    g_w1h[t] = pack_hi(a.x, a.y);
    g_w1l[t] = pack_lo(a.x, a.y);
    g_w2h[t] = pack_hi(b.x, b.y);
    g_w2l[t] = pack_lo(b.x, b.y);
}

__global__ void k_hist(const int* __restrict__ ei) {
    int e = blockIdx.x * blockDim.x + threadIdx.x;
    if (e >= N_EDGES) return;
    atomicAdd(&g_counts[ei[N_EDGES + e]], 1);
}
__global__ void k_scan1() {
    __shared__ int sm[1024];
    int t = threadIdx.x;
    int gid = blockIdx.x * 1024 + t;
    int v = (gid < N_NODES) ? g_counts[gid] : 0;
    sm[t] = v;
    __syncthreads();
    for (int off = 1; off < 1024; off <<= 1) {
        int add = (t >= off) ? sm[t - off] : 0;
        __syncthreads();
        sm[t] += add;
        __syncthreads();
    }
    if (gid < N_NODES) g_row[gid] = sm[t] - v;
    if (t == 1023) g_bsums[blockIdx.x] = sm[1023];
}
__global__ void k_scan2(int nb) {
    __shared__ int sm[64];
    int t = threadIdx.x;
    int v = (t < nb) ? g_bsums[t] : 0;
    sm[t] = v;
    __syncthreads();
    for (int off = 1; off < 64; off <<= 1) {
        int add = (t >= off) ? sm[t - off] : 0;
        __syncthreads();
        sm[t] += add;
        __syncthreads();
    }
    if (t < nb) g_bsums[t] = sm[t] - v;
}
__global__ void k_scan3() {
    int gid = blockIdx.x * blockDim.x + threadIdx.x;
    if (gid < N_NODES) {
        int r = g_row[gid] + g_bsums[gid >> 10];
        g_row[gid] = r;
        g_cursor[gid] = r;
    }
    if (gid == 0) g_row[N_NODES] = N_EDGES;
}
__global__ void k_scatter(const int* __restrict__ ei, const int* __restrict__ ea) {
    int e = blockIdx.x * blockDim.x + threadIdx.x;
    if (e >= N_EDGES) return;
    int d = ei[N_EDGES + e];
    int p = atomicAdd(&g_cursor[d], 1);
    g_csr_src[p] = ei[e];
    g_csr_ea[p]  = ea[2 * e] + (ea[2 * e + 1] << 3);
}

// one warp per node; emits agg as hi/lo bf16 planes; block 0 zeroes stats
__global__ void __launch_bounds__(256) k_agg(const float* __restrict__ e1l,
                                             const float* __restrict__ e2l) {
    __shared__ float4 se[10 * DIM4];
    int tid = threadIdx.x;
    if (blockIdx.x == 0 && tid < 2 * DIM) g_stats[tid] = 0.f;
    for (int i = tid; i < 10 * DIM4; i += 256) {
        const float* src = (i < 6 * DIM4) ? (e1l + i * 4) : (e2l + (i - 6 * DIM4) * 4);
        se[i] = *(const float4*)src;
    }
    __syncthreads();
    int warp = tid >> 5, lane = tid & 31;
    int v = blockIdx.x * 8 + warp;
    if (v >= N_NODES) return;
    int s0 = g_row[v], s1 = g_row[v + 1];
    float4 acc = make_float4(0.f, 0.f, 0.f, 0.f);
    for (int e = s0; e < s1; e++) {
        int s  = g_csr_src[e];
        int at = g_csr_ea[e];
        float4 hv = ((const float4*)g_h)[s * DIM4 + lane];
        float4 t1 = se[(at & 7) * DIM4 + lane];
        float4 t2 = se[6 * DIM4 + (at >> 3) * DIM4 + lane];
        acc.x += hv.x + t1.x + t2.x;
        acc.y += hv.y + t1.y + t2.y;
        acc.z += hv.z + t1.z + t2.z;
        acc.w += hv.w + t1.w + t2.w;
    }
    uint2 hi, lo;
    hi.x = pack_hi(acc.x, acc.y); hi.y = pack_hi(acc.z, acc.w);
    lo.x = pack_lo(acc.x, acc.y); lo.y = pack_lo(acc.z, acc.w);
    ((uint2*)g_aggh)[v * 32 + lane] = hi;
    ((uint2*)g_aggl)[v * 32 + lane] = lo;
}

// ---------------- fused MLP kernel ----------------
// h2 = relu(agg @ W1 + b1) @ W2 + b2, with fused BN-stats. grid 391, 256 thr.
// SMEM regions (each plane 34816B): R0 = A planes / later mid tile1,
// R1 = weight staging, R2 = mid tile0.
#define LDT 136
#define ROWB (LDT * 2)            // 272B smem row stride
#define PLANE (128 * ROWB)        // 34816
#define SMEMF (6 * PLANE)         // 208896

__global__ void __launch_bounds__(256, 1) k_fused(
    int M,
    const uint32_t* __restrict__ ah_g, const uint32_t* __restrict__ al_g,
    const uint32_t* __restrict__ w1h, const uint32_t* __restrict__ w1l,
    const uint32_t* __restrict__ w2h, const uint32_t* __restrict__ w2l,
    const float* __restrict__ b1, const float* __restrict__ b2,
    float* __restrict__ C) {
    extern __shared__ char smem[];
    const uint32_t sb = smem_u32(smem);
    const uint32_t R0H = sb,             R0L = sb + PLANE;
    const uint32_t R1H = sb + 2 * PLANE, R1L = sb + 3 * PLANE;
    const uint32_t R2H = sb + 4 * PLANE, R2L = sb + 5 * PLANE;
    char* p0H = smem;
    char* p0L = smem + PLANE;
    char* p1H = smem + 2 * PLANE;
    char* p1L = smem + 3 * PLANE;
    char* p2H = smem + 4 * PLANE;
    char* p2L = smem + 5 * PLANE;

    const int tid = threadIdx.x, wid = tid >> 5, lane = tid & 31;
    const int wm = wid >> 2, wn = wid & 3;
    const int rowBase = blockIdx.x << 7;

    const int arow = wm * 64 + (lane & 15);
    const int acolSel = (lane >> 4) << 3;
    const int brow = lane & 15;
    const int rLoc  = wm * 64 + (lane >> 2);          // local out row base
    const int cLoc  = wn * 32 + (lane & 3) * 2;       // local out col base

    float acc[4][4][4];

    // ---- step 1: fill A planes (R0) + W1 half0 (R1) ----
#pragma unroll
    for (int it = 0; it < 8; it++) {
        int g = tid + it * 256;
        int r = g >> 4, c = g & 15;
        uint4 hv = make_uint4(0, 0, 0, 0), lv = hv;
        if (rowBase + r < M) {
            size_t src = (size_t)(rowBase + r) * 16 + c;
            hv = ((const uint4*)ah_g)[src];
            lv = ((const uint4*)al_g)[src];
        }
        int off = r * ROWB + c * 16;
        *(uint4*)(p0H + off) = hv;
        *(uint4*)(p0L + off) = lv;
    }
#pragma unroll
    for (int it = 0; it < 8; it++) {
        int g = tid + it * 256;
        int k = g >> 4, c = g & 15;
        size_t src = (size_t)k * 32 + c;              // bx=0 half
        int off = k * ROWB + c * 16;
        *(uint4*)(p1H + off) = ((const uint4*)w1h)[src];
        *(uint4*)(p1L + off) = ((const uint4*)w1l)[src];
    }
    __syncthreads();

    // ---- GEMM1 over the two N-halves of W1 ----
#pragma unroll
    for (int bx = 0; bx < 2; bx++) {
#pragma unroll
        for (int i = 0; i < 4; i++)
#pragma unroll
            for (int j = 0; j < 4; j++)
#pragma unroll
                for (int k = 0; k < 4; k++) acc[i][j][k] = 0.f;
#pragma unroll
        for (int kk = 0; kk < 8; kk++) {
            uint32_t ah[4][4], al[4][4], bh[4][2], bl[4][2];
            int acol = kk * 16 + acolSel;
#pragma unroll
            for (int mi = 0; mi < 4; mi++) {
                uint32_t ao = (uint32_t)((arow + mi * 16) * ROWB + acol * 2);
                ldsm4(ah[mi], R0H + ao);
                ldsm4(al[mi], R0L + ao);
            }
#pragma unroll
            for (int ni = 0; ni < 4; ni++) {
                uint32_t bo = (uint32_t)((kk * 16 + brow) * ROWB + (wn * 32 + ni * 8) * 2);
                ldsm2t(bh[ni], R1H + bo);
                ldsm2t(bl[ni], R1L + bo);
            }
#pragma unroll
            for (int mi = 0; mi < 4; mi++)
#pragma unroll
                for (int ni = 0; ni < 4; ni++) {
                    mma_bf16(acc[mi][ni], ah[mi], bh[ni]);
                    mma_bf16(acc[mi][ni], ah[mi], bl[ni]);
                    mma_bf16(acc[mi][ni], al[mi], bh[ni]);
                }
        }
        __syncthreads();   // everyone done reading R0/R1 for this half

        // pack mid tile: bx==0 -> R2; bx==1 -> R0 (A dead after second mma)
        char* mH = bx ? p0H : p2H;
        char* mL = bx ? p0L : p2L;
#pragma unroll
        for (int mi = 0; mi < 4; mi++)
#pragma unroll
            for (int h = 0; h < 2; h++) {
                int rowl = rLoc + mi * 16 + h * 8;
#pragma unroll
                for (int ni = 0; ni < 4; ni++) {
                    int col = cLoc + ni * 8;
                    float ox = fmaxf(acc[mi][ni][2 * h + 0] + b1[bx * 128 + col], 0.f);
                    float oy = fmaxf(acc[mi][ni][2 * h + 1] + b1[bx * 128 + col + 1], 0.f);
                    int off = rowl * ROWB + col * 2;
                    *(uint32_t*)(mH + off) = pack_hi(ox, oy);
                    *(uint32_t*)(mL + off) = pack_lo(ox, oy);
                }
            }
        if (bx == 0) {
            // stage W1 half1 into R1
#pragma unroll
            for (int it = 0; it < 8; it++) {
                int g = tid + it * 256;
                int k = g >> 4, c = g & 15;
                size_t src = (size_t)k * 32 + 16 + c;
                int off = k * ROWB + c * 16;
                *(uint4*)(p1H + off) = ((const uint4*)w1h)[src];
                *(uint4*)(p1L + off) = ((const uint4*)w1l)[src];
            }
        }
        __syncthreads();
    }

    // ---- GEMM2: h2 = mid @ W2 + b2, K = 256 in two chunks ----
#pragma unroll
    for (int i = 0; i < 4; i++)
#pragma unroll
        for (int j = 0; j < 4; j++)
#pragma unroll
            for (int k = 0; k < 4; k++) acc[i][j][k] = 0.f;

#pragma unroll
    for (int ch = 0; ch < 2; ch++) {
        // stage W2 chunk into R1 (R1 free: W1 reads finished before last sync)
#pragma unroll
        for (int it = 0; it < 8; it++) {
            int g = tid + it * 256;
            int k = g >> 4, c = g & 15;
            size_t src = (size_t)(ch * 128 + k) * 16 + c;
            int off = k * ROWB + c * 16;
            *(uint4*)(p1H + off) = ((const uint4*)w2h)[src];
            *(uint4*)(p1L + off) = ((const uint4*)w2l)[src];
        }
        __syncthreads();

        const uint32_t MH = ch ? R0H : R2H;
        const uint32_t ML = ch ? R0L : R2L;
#pragma unroll
        for (int kk = 0; kk < 8; kk++) {
            uint32_t ah[4][4], al[4][4], bh[4][2], bl[4][2];
            int acol = kk * 16 + acolSel;
#pragma unroll
            for (int mi = 0; mi < 4; mi++) {
                uint32_t ao = (uint32_t)((arow + mi * 16) * ROWB + acol * 2);
                ldsm4(ah[mi], MH + ao);
                ldsm4(al[mi], ML + ao);
            }
#pragma unroll
            for (int ni = 0; ni < 4; ni++) {
                uint32_t bo = (uint32_t)((kk * 16 + brow) * ROWB + (wn * 32 + ni * 8) * 2);
                ldsm2t(bh[ni], R1H + bo);
                ldsm2t(bl[ni], R1L + bo);
            }
#pragma unroll
            for (int mi = 0; mi < 4; mi++)
#pragma unroll
                for (int ni = 0; ni < 4; ni++) {
                    mma_bf16(acc[mi][ni], ah[mi], bh[ni]);
                    mma_bf16(acc[mi][ni], ah[mi], bl[ni]);
                    mma_bf16(acc[mi][ni], al[mi], bh[ni]);
                }
        }
        __syncthreads();   // before R1 overwrite next chunk
    }

    // ---- epilogue: store h2 + column sums/sumsq -> g_stats ----
    const int rBase = rowBase + rLoc;
    float csum[4][2], csq[4][2];
#pragma unroll
    for (int ni = 0; ni < 4; ni++) {
        csum[ni][0] = csum[ni][1] = 0.f;
        csq[ni][0] = csq[ni][1] = 0.f;
    }
#pragma unroll
    for (int mi = 0; mi < 4; mi++)
#pragma unroll
        for (int h = 0; h < 2; h++) {
            int row = rBase + mi * 16 + h * 8;
            if (row < M) {
#pragma unroll
                for (int ni = 0; ni < 4; ni++) {
                    int col = cLoc + ni * 8;
                    float2 o;
                    o.x = acc[mi][ni][2 * h + 0] + b2[col];
                    o.y = acc[mi][ni][2 * h + 1] + b2[col + 1];
                    *(float2*)(C + (size_t)row * 128 + col) = o;
                    csum[ni][0] += o.x; csq[ni][0] += o.x * o.x;
                    csum[ni][1] += o.y; csq[ni][1] += o.y * o.y;
                }
            }
        }
#pragma unroll
    for (int ni = 0; ni < 4; ni++)
#pragma unroll
        for (int pp = 0; pp < 2; pp++) {
            float s = csum[ni][pp], q = csq[ni][pp];
            s += __shfl_xor_sync(0xFFFFFFFF, s, 4);
            q += __shfl_xor_sync(0xFFFFFFFF, q, 4);
            s += __shfl_xor_sync(0xFFFFFFFF, s, 8);
            q += __shfl_xor_sync(0xFFFFFFFF, q, 8);
            s += __shfl_xor_sync(0xFFFFFFFF, s, 16);
            q += __shfl_xor_sync(0xFFFFFFFF, q, 16);
            if ((lane >> 2) == 0) {
                int col = cLoc + ni * 8 + pp;
                atomicAdd(&g_stats[col], s);
                atomicAdd(&g_stats[DIM + col], q);
            }
        }
}

// ---------------- BN apply (every layer; relu on all but last) ----------------
__global__ void k_bn(const float* __restrict__ h2,
                     const float* __restrict__ gamma,
                     const float* __restrict__ beta,
                     float* __restrict__ out, int relu) {
    __shared__ float sc[DIM], sh[DIM];
    int tid = threadIdx.x;
    if (tid < DIM) {
        float mu  = g_stats[tid] * (1.0f / N_NODES);
        float var = g_stats[DIM + tid] * (1.0f / N_NODES) - mu * mu;
        float s = gamma[tid] * rsqrtf(var + BN_EPS);
        sc[tid] = s;
        sh[tid] = beta[tid] - mu * s;
    }
    __syncthreads();
    int i = blockIdx.x * blockDim.x + tid;
    if (i >= N_NODES * DIM4) return;
    int c = (i & 31) * 4;
    float4 v = ((const float4*)h2)[i];
    v.x = v.x * sc[c + 0] + sh[c + 0];
    v.y = v.y * sc[c + 1] + sh[c + 1];
    v.z = v.z * sc[c + 2] + sh[c + 2];
    v.w = v.w * sc[c + 3] + sh[c + 3];
    if (relu) {
        v.x = fmaxf(v.x, 0.f); v.y = fmaxf(v.y, 0.f);
        v.z = fmaxf(v.z, 0.f); v.w = fmaxf(v.w, 0.f);
    }
    ((float4*)out)[i] = v;
}

// ---------------- launch ----------------
extern "C" void kernel_launch(void* const* d_in, const int* in_sizes, int n_in,
                              void* d_out, int out_size) {
    const int*   x     = (const int*)d_in[0];
    const int*   ei    = (const int*)d_in[1];
    const int*   ea    = (const int*)d_in[2];
    const float* atom  = (const float*)d_in[3];
    const float* chir  = (const float*)d_in[4];
    const float* hyb   = (const float*)d_in[5];
    const float* e1    = (const float*)d_in[6];
    const float* e2    = (const float*)d_in[7];
    const float* W1    = (const float*)d_in[8];
    const float* b1    = (const float*)d_in[9];
    const float* W2    = (const float*)d_in[10];
    const float* b2    = (const float*)d_in[11];
    const float* gamma = (const float*)d_in[12];
    const float* beta  = (const float*)d_in[13];
    float* out = (float*)d_out;

    float *pH2, *pH;
    uint32_t *pAh, *pAl, *pW1h, *pW1l, *pW2h, *pW2l;
    cudaGetSymbolAddress((void**)&pH2,  g_h2);
    cudaGetSymbolAddress((void**)&pH,   g_h);
    cudaGetSymbolAddress((void**)&pAh,  g_aggh);
    cudaGetSymbolAddress((void**)&pAl,  g_aggl);
    cudaGetSymbolAddress((void**)&pW1h, g_w1h);
    cudaGetSymbolAddress((void**)&pW1l, g_w1l);
    cudaGetSymbolAddress((void**)&pW2h, g_w2h);
    cudaGetSymbolAddress((void**)&pW2l, g_w2l);

    cudaFuncSetAttribute(k_fused, cudaFuncAttributeMaxDynamicSharedMemorySize, SMEMF);

    const int TPB = 256;
    int nbE = (N_EDGES + TPB - 1) / TPB;
    int nbN = (N_NODES + TPB - 1) / TPB;
    int nbF4 = (N_NODES * DIM4) / TPB;

    k_init_h<<<nbF4, TPB>>>(x, atom, chir, hyb);
    k_wconv<<<320, 256>>>(W1, W2);
    k_hist<<<nbE, TPB>>>(ei);
    int scanBlocks = (N_NODES + 1023) / 1024;
    k_scan1<<<scanBlocks, 1024>>>();
    k_scan2<<<1, 64>>>(scanBlocks);
    k_scan3<<<nbN, TPB>>>();
    k_scatter<<<nbE, TPB>>>(ei, ea);

    int gemmRows = (N_NODES + 127) / 128;   // 391
    for (int l = 0; l < NLAYER; l++) {
        k_agg<<<(N_NODES + 7) / 8, 256>>>(e1 + (size_t)l * 6 * DIM,
                                          e2 + (size_t)l * 4 * DIM);
        k_fused<<<gemmRows, 256, SMEMF>>>(
            N_NODES, pAh, pAl,
            pW1h + l * 16384, pW1l + l * 16384,
            pW2h + l * 16384, pW2l + l * 16384,
            b1 + (size_t)l * 2 * DIM, b2 + (size_t)l * DIM, pH2);
        int last = (l == NLAYER - 1);
        k_bn<<<nbF4, TPB>>>(pH2, gamma + (size_t)l * DIM, beta + (size_t)l * DIM,
                            last ? out : pH, last ? 0 : 1);
    }
}